// round 4
// baseline (speedup 1.0000x reference)
#include <cuda_runtime.h>

#define BB 64
#define SS 512
#define II 1024
#define HH 1024
#define NG 4096          // 4*H
#define MMR (BB*SS)      // 32768

// ---------------- device scratch (no allocs allowed) ----------------
__device__ __align__(16) float g_Up[(size_t)NG * II];       // U_all^T  [n][k], tf32-rounded
__device__ __align__(16) float g_Wp[(size_t)NG * HH];       // W_all^T  [n][k], tf32-rounded
__device__ __align__(16) float g_xp[(size_t)MMR * NG];      // x_proj   [(s*64+b)][4H]  (512 MB)
__device__ __align__(16) float g_h[2][BB * HH];             // double-buffered hidden state
__device__ __align__(16) float g_c[BB * HH];                // cell state

// ---------------- helpers ----------------
__device__ __forceinline__ float tf32r(float f) {
    unsigned u;
    asm("cvt.rna.tf32.f32 %0, %1;" : "=r"(u) : "f"(f));
    return __uint_as_float(u);
}

__device__ __forceinline__ void mma8(float* d, const unsigned* a, const unsigned* b) {
    asm volatile(
        "mma.sync.aligned.m16n8k8.row.col.f32.tf32.tf32.f32 "
        "{%0,%1,%2,%3}, {%4,%5,%6,%7}, {%8,%9}, {%0,%1,%2,%3};"
        : "+f"(d[0]), "+f"(d[1]), "+f"(d[2]), "+f"(d[3])
        : "r"(a[0]), "r"(a[1]), "r"(a[2]), "r"(a[3]), "r"(b[0]), "r"(b[1]));
}

__device__ __forceinline__ float sigmf(float x) { return 1.f / (1.f + __expf(-x)); }

// ---------------- pack: build K-major tf32 U_all^T / W_all^T ----------------
// z in [0,8): z<4 -> U gate z, z>=4 -> W gate z-4. 32x32 tiles via smem transpose.
__global__ void pack_kernel(
    const float* __restrict__ Uf, const float* __restrict__ Ui,
    const float* __restrict__ Uc, const float* __restrict__ Uo,
    const float* __restrict__ Wf, const float* __restrict__ Wi,
    const float* __restrict__ Wc, const float* __restrict__ Wo)
{
    __shared__ float t[32][33];
    int z = blockIdx.z;
    int g = z & 3;
    const float* src;
    float* dst;
    if (z < 4) { src = (g == 0) ? Uf : (g == 1) ? Ui : (g == 2) ? Uc : Uo; dst = g_Up; }
    else       { src = (g == 0) ? Wf : (g == 1) ? Wi : (g == 2) ? Wc : Wo; dst = g_Wp; }
    int n0 = blockIdx.x * 32, k0 = blockIdx.y * 32;
    int tx = threadIdx.x, ty = threadIdx.y;   // 32 x 8
    #pragma unroll
    for (int i = 0; i < 4; i++) {
        int kr = ty + i * 8;
        t[kr][tx] = src[(size_t)(k0 + kr) * HH + n0 + tx];
    }
    __syncthreads();
    #pragma unroll
    for (int i = 0; i < 4; i++) {
        int nr = ty + i * 8;
        dst[(size_t)(g * HH + n0 + nr) * II + k0 + tx] = tf32r(t[tx][nr]);
    }
}

__global__ void init_kernel() {
    int i = blockIdx.x * blockDim.x + threadIdx.x;
    if (i < BB * HH) { g_h[0][i] = 0.f; g_c[i] = 0.f; }
}

// ---------------- phase 1: x_proj = x @ U_all + b ----------------
// C[32768,4096] tiles 128x128, 256 thr (8 warps, 4x2), warp tile 32x64.
__global__ __launch_bounds__(256, 2) void xproj_kernel(
    const float* __restrict__ x,
    const float* __restrict__ bf, const float* __restrict__ bi,
    const float* __restrict__ bc, const float* __restrict__ bo)
{
    __shared__ float As[2][128][20];
    __shared__ float Bs[2][128][20];
    const int tid = threadIdx.x, lane = tid & 31, warp = tid >> 5;
    const int wm = warp >> 1, wn = warp & 1;
    const int gq = lane >> 2, tq = lane & 3;
    const int m0 = blockIdx.y * 128, n0 = blockIdx.x * 128;

    float acc[2][8][4];
    #pragma unroll
    for (int a = 0; a < 2; a++)
        #pragma unroll
        for (int b = 0; b < 8; b++)
            #pragma unroll
            for (int c = 0; c < 4; c++) acc[a][b][c] = 0.f;

    float4 ra[2], rb[2];
    #pragma unroll
    for (int it = 0; it < 2; it++) {
        int idx = tid + it * 256, row = idx >> 2, kq = idx & 3;
        ra[it] = *(const float4*)(x    + (size_t)(m0 + row) * II + kq * 4);
        rb[it] = *(const float4*)(g_Up + (size_t)(n0 + row) * II + kq * 4);
    }
    #pragma unroll
    for (int it = 0; it < 2; it++) {
        int idx = tid + it * 256, row = idx >> 2, kq = idx & 3;
        As[0][row][kq*4+0] = tf32r(ra[it].x); As[0][row][kq*4+1] = tf32r(ra[it].y);
        As[0][row][kq*4+2] = tf32r(ra[it].z); As[0][row][kq*4+3] = tf32r(ra[it].w);
        Bs[0][row][kq*4+0] = rb[it].x; Bs[0][row][kq*4+1] = rb[it].y;
        Bs[0][row][kq*4+2] = rb[it].z; Bs[0][row][kq*4+3] = rb[it].w;
    }
    __syncthreads();

    const int NK = II / 16;
    for (int kc = 0; kc < NK; kc++) {
        int buf = kc & 1;
        if (kc + 1 < NK) {
            int k0 = (kc + 1) * 16;
            #pragma unroll
            for (int it = 0; it < 2; it++) {
                int idx = tid + it * 256, row = idx >> 2, kq = idx & 3;
                ra[it] = *(const float4*)(x    + (size_t)(m0 + row) * II + k0 + kq * 4);
                rb[it] = *(const float4*)(g_Up + (size_t)(n0 + row) * II + k0 + kq * 4);
            }
        }
        #pragma unroll
        for (int kk = 0; kk < 16; kk += 8) {
            unsigned a[2][4], b[8][2];
            #pragma unroll
            for (int mf = 0; mf < 2; mf++) {
                int r = wm * 32 + mf * 16 + gq;
                a[mf][0] = __float_as_uint(As[buf][r    ][kk + tq]);
                a[mf][1] = __float_as_uint(As[buf][r + 8][kk + tq]);
                a[mf][2] = __float_as_uint(As[buf][r    ][kk + tq + 4]);
                a[mf][3] = __float_as_uint(As[buf][r + 8][kk + tq + 4]);
            }
            #pragma unroll
            for (int nf = 0; nf < 8; nf++) {
                int c = wn * 64 + nf * 8 + gq;
                b[nf][0] = __float_as_uint(Bs[buf][c][kk + tq]);
                b[nf][1] = __float_as_uint(Bs[buf][c][kk + tq + 4]);
            }
            #pragma unroll
            for (int mf = 0; mf < 2; mf++)
                #pragma unroll
                for (int nf = 0; nf < 8; nf++)
                    mma8(acc[mf][nf], a[mf], b[nf]);
        }
        if (kc + 1 < NK) {
            int nb = buf ^ 1;
            #pragma unroll
            for (int it = 0; it < 2; it++) {
                int idx = tid + it * 256, row = idx >> 2, kq = idx & 3;
                As[nb][row][kq*4+0] = tf32r(ra[it].x); As[nb][row][kq*4+1] = tf32r(ra[it].y);
                As[nb][row][kq*4+2] = tf32r(ra[it].z); As[nb][row][kq*4+3] = tf32r(ra[it].w);
                Bs[nb][row][kq*4+0] = rb[it].x; Bs[nb][row][kq*4+1] = rb[it].y;
                Bs[nb][row][kq*4+2] = rb[it].z; Bs[nb][row][kq*4+3] = rb[it].w;
            }
        }
        __syncthreads();
    }

    // epilogue: +bias, scatter to (s*64+b) row order
    #pragma unroll
    for (int mf = 0; mf < 2; mf++) {
        int mr = m0 + wm * 32 + mf * 16 + gq;
        int m1 = mr + 8;
        size_t r0 = (size_t)(((mr & 511) << 6) | (mr >> 9)) * NG;
        size_t r1 = (size_t)(((m1 & 511) << 6) | (m1 >> 9)) * NG;
        #pragma unroll
        for (int nf = 0; nf < 8; nf++) {
            int c0 = n0 + wn * 64 + nf * 8 + 2 * tq;
            int gate = c0 >> 10;
            const float* bp = (gate == 0) ? bf : (gate == 1) ? bi : (gate == 2) ? bc : bo;
            float bv0 = bp[c0 & 1023], bv1 = bp[(c0 + 1) & 1023];
            g_xp[r0 + c0    ] = acc[mf][nf][0] + bv0;
            g_xp[r0 + c0 + 1] = acc[mf][nf][1] + bv1;
            g_xp[r1 + c0    ] = acc[mf][nf][2] + bv0;
            g_xp[r1 + c0 + 1] = acc[mf][nf][3] + bv1;
        }
    }
}

// ---------------- recurrent step: g = h@W_all + xp[s]; fused gates ----------------
// 128 CTAs x 128 thr. CTA j owns hidden cols [8j,8j+8) across all 4 gates, so each
// thread's f/i/c~/o fragments align elementwise -> register-local cell update.
__global__ __launch_bounds__(128) void step_kernel(int s, float* __restrict__ out_hs)
{
    __shared__ float As[2][64][36];
    __shared__ float Bs[2][32][36];
    const int tid = threadIdx.x, lane = tid & 31, w = tid >> 5;
    const int gq = lane >> 2, tq = lane & 3;
    const int j = blockIdx.x;
    const float* __restrict__ h_old = g_h[s & 1];
    float* __restrict__ h_new = g_h[(s + 1) & 1];

    float acc[4][4];
    #pragma unroll
    for (int g = 0; g < 4; g++)
        #pragma unroll
        for (int p = 0; p < 4; p++) acc[g][p] = 0.f;

    float4 ra[4], rb[2];
    #pragma unroll
    for (int it = 0; it < 4; it++) {
        int idx = tid + it * 128, row = idx >> 3, kq = idx & 7;
        ra[it] = *(const float4*)(h_old + (size_t)row * HH + kq * 4);
    }
    #pragma unroll
    for (int it = 0; it < 2; it++) {
        int idx = tid + it * 128, row = idx >> 3, kq = idx & 7;
        int n = (row >> 3) * 1024 + j * 8 + (row & 7);
        rb[it] = *(const float4*)(g_Wp + (size_t)n * HH + kq * 4);
    }
    #pragma unroll
    for (int it = 0; it < 4; it++) {
        int idx = tid + it * 128, row = idx >> 3, kq = idx & 7;
        As[0][row][kq*4+0] = tf32r(ra[it].x); As[0][row][kq*4+1] = tf32r(ra[it].y);
        As[0][row][kq*4+2] = tf32r(ra[it].z); As[0][row][kq*4+3] = tf32r(ra[it].w);
    }
    #pragma unroll
    for (int it = 0; it < 2; it++) {
        int idx = tid + it * 128, row = idx >> 3, kq = idx & 7;
        Bs[0][row][kq*4+0] = rb[it].x; Bs[0][row][kq*4+1] = rb[it].y;
        Bs[0][row][kq*4+2] = rb[it].z; Bs[0][row][kq*4+3] = rb[it].w;
    }
    __syncthreads();

    const int NK = HH / 32;
    for (int kc = 0; kc < NK; kc++) {
        int buf = kc & 1;
        if (kc + 1 < NK) {
            int k0 = (kc + 1) * 32;
            #pragma unroll
            for (int it = 0; it < 4; it++) {
                int idx = tid + it * 128, row = idx >> 3, kq = idx & 7;
                ra[it] = *(const float4*)(h_old + (size_t)row * HH + k0 + kq * 4);
            }
            #pragma unroll
            for (int it = 0; it < 2; it++) {
                int idx = tid + it * 128, row = idx >> 3, kq = idx & 7;
                int n = (row >> 3) * 1024 + j * 8 + (row & 7);
                rb[it] = *(const float4*)(g_Wp + (size_t)n * HH + k0 + kq * 4);
            }
        }
        #pragma unroll
        for (int kk = 0; kk < 32; kk += 8) {
            unsigned a[4];
            int r = w * 16 + gq;
            a[0] = __float_as_uint(As[buf][r    ][kk + tq]);
            a[1] = __float_as_uint(As[buf][r + 8][kk + tq]);
            a[2] = __float_as_uint(As[buf][r    ][kk + tq + 4]);
            a[3] = __float_as_uint(As[buf][r + 8][kk + tq + 4]);
            #pragma unroll
            for (int g = 0; g < 4; g++) {
                unsigned b[2];
                b[0] = __float_as_uint(Bs[buf][g * 8 + gq][kk + tq]);
                b[1] = __float_as_uint(Bs[buf][g * 8 + gq][kk + tq + 4]);
                mma8(acc[g], a, b);
            }
        }
        if (kc + 1 < NK) {
            int nb = buf ^ 1;
            #pragma unroll
            for (int it = 0; it < 4; it++) {
                int idx = tid + it * 128, row = idx >> 3, kq = idx & 7;
                As[nb][row][kq*4+0] = tf32r(ra[it].x); As[nb][row][kq*4+1] = tf32r(ra[it].y);
                As[nb][row][kq*4+2] = tf32r(ra[it].z); As[nb][row][kq*4+3] = tf32r(ra[it].w);
            }
            #pragma unroll
            for (int it = 0; it < 2; it++) {
                int idx = tid + it * 128, row = idx >> 3, kq = idx & 7;
                Bs[nb][row][kq*4+0] = rb[it].x; Bs[nb][row][kq*4+1] = rb[it].y;
                Bs[nb][row][kq*4+2] = rb[it].z; Bs[nb][row][kq*4+3] = rb[it].w;
            }
        }
        __syncthreads();
    }

    // fused gate epilogue (register-local across the 4 gate fragments)
    const float* __restrict__ xp = g_xp + (size_t)(s * 64) * NG;
    #pragma unroll
    for (int p = 0; p < 4; p++) {
        int brow = w * 16 + gq + ((p & 2) ? 8 : 0);
        int col  = j * 8 + 2 * tq + (p & 1);
        size_t xo = (size_t)brow * NG + col;
        float gf = acc[0][p] + xp[xo];
        float gi = acc[1][p] + xp[xo + 1024];
        float gc = acc[2][p] + xp[xo + 2048];
        float go = acc[3][p] + xp[xo + 3072];
        float fg = sigmf(gf), ig = sigmf(gi), og = sigmf(go);
        float Ct = tanhf(gc);
        int ci = brow * HH + col;
        float cn = fg * g_c[ci] + ig * Ct;
        g_c[ci] = cn;
        float hn = og * tanhf(cn);
        h_new[ci] = hn;
        out_hs[((size_t)brow * SS + s) * HH + col] = hn;
    }
}

__global__ void final_kernel(float* __restrict__ out) {
    int i = blockIdx.x * blockDim.x + threadIdx.x;
    if (i < BB * HH) {
        out[i] = g_h[0][i];           // h_T (512 steps -> parity 0)
        out[BB * HH + i] = g_c[i];    // c_T
    }
}

// ---------------- launch ----------------
extern "C" void kernel_launch(void* const* d_in, const int* in_sizes, int n_in,
                              void* d_out, int out_size)
{
    const float* x  = (const float*)d_in[0];
    const float* Uf = (const float*)d_in[1];
    const float* Ui = (const float*)d_in[2];
    const float* Uc = (const float*)d_in[3];
    const float* Uo = (const float*)d_in[4];
    const float* Wf = (const float*)d_in[5];
    const float* Wi = (const float*)d_in[6];
    const float* Wc = (const float*)d_in[7];
    const float* Wo = (const float*)d_in[8];
    const float* bf = (const float*)d_in[9];
    const float* bi = (const float*)d_in[10];
    const float* bc = (const float*)d_in[11];
    const float* bo = (const float*)d_in[12];
    float* out = (float*)d_out;

    pack_kernel<<<dim3(32, 32, 8), dim3(32, 8)>>>(Uf, Ui, Uc, Uo, Wf, Wi, Wc, Wo);
    init_kernel<<<(BB * HH + 255) / 256, 256>>>();
    xproj_kernel<<<dim3(NG / 128, MMR / 128), 256>>>(x, bf, bi, bc, bo);

    float* hs = out + 2 * BB * HH;   // hidden_seq region
    for (int s = 0; s < SS; s++)
        step_kernel<<<128, 128>>>(s, hs);

    final_kernel<<<(BB * HH + 255) / 256, 256>>>(out);
}

// round 5
// speedup vs baseline: 1.4692x; 1.4692x over previous
#include <cuda_runtime.h>

#define BB 64
#define SS 512
#define II 1024
#define HH 1024
#define NG 4096          // 4*H
#define MMR (BB*SS)      // 32768
#define NCTA 128
#define PTHR 256

// ---------------- device scratch (no allocs allowed) ----------------
__device__ __align__(16) float g_Up[(size_t)NG * II];       // U_all^T  [n][k], tf32-rounded
__device__ __align__(16) float g_Wp[(size_t)NG * HH];       // W_all^T  [n][k], tf32-rounded
__device__ __align__(16) float g_xp[(size_t)MMR * NG];      // x_proj   [(s*64+b)][4H]
__device__ __align__(16) float g_h[2][BB * HH];             // double-buffered hidden state
__device__ __align__(16) float g_c[BB * HH];                // cell state
__device__ unsigned g_cnt;                                   // grid barrier arrivals
__device__ unsigned g_gen;                                   // grid barrier generation

// ---------------- helpers ----------------
__device__ __forceinline__ float tf32r(float f) {
    unsigned u;
    asm("cvt.rna.tf32.f32 %0, %1;" : "=r"(u) : "f"(f));
    return __uint_as_float(u);
}

__device__ __forceinline__ void mma8(float* d, const unsigned* a, const unsigned* b) {
    asm volatile(
        "mma.sync.aligned.m16n8k8.row.col.f32.tf32.tf32.f32 "
        "{%0,%1,%2,%3}, {%4,%5,%6,%7}, {%8,%9}, {%0,%1,%2,%3};"
        : "+f"(d[0]), "+f"(d[1]), "+f"(d[2]), "+f"(d[3])
        : "r"(a[0]), "r"(a[1]), "r"(a[2]), "r"(a[3]), "r"(b[0]), "r"(b[1]));
}

__device__ __forceinline__ float sigmf(float x) { return 1.f / (1.f + __expf(-x)); }

// ---------------- pack: build K-major tf32 U_all^T / W_all^T ----------------
__global__ void pack_kernel(
    const float* __restrict__ Uf, const float* __restrict__ Ui,
    const float* __restrict__ Uc, const float* __restrict__ Uo,
    const float* __restrict__ Wf, const float* __restrict__ Wi,
    const float* __restrict__ Wc, const float* __restrict__ Wo)
{
    __shared__ float t[32][33];
    int z = blockIdx.z;
    int g = z & 3;
    const float* src;
    float* dst;
    if (z < 4) { src = (g == 0) ? Uf : (g == 1) ? Ui : (g == 2) ? Uc : Uo; dst = g_Up; }
    else       { src = (g == 0) ? Wf : (g == 1) ? Wi : (g == 2) ? Wc : Wo; dst = g_Wp; }
    int n0 = blockIdx.x * 32, k0 = blockIdx.y * 32;
    int tx = threadIdx.x, ty = threadIdx.y;   // 32 x 8
    #pragma unroll
    for (int i = 0; i < 4; i++) {
        int kr = ty + i * 8;
        t[kr][tx] = src[(size_t)(k0 + kr) * HH + n0 + tx];
    }
    __syncthreads();
    #pragma unroll
    for (int i = 0; i < 4; i++) {
        int nr = ty + i * 8;
        dst[(size_t)(g * HH + n0 + nr) * II + k0 + tx] = tf32r(t[tx][nr]);
    }
}

__global__ void init_kernel() {
    int i = blockIdx.x * blockDim.x + threadIdx.x;
    if (i < BB * HH) { g_h[0][i] = 0.f; g_c[i] = 0.f; }
    if (i == 0) { g_cnt = 0u; g_gen = 0u; }
}

// ---------------- phase 1: x_proj = x @ U_all + b ----------------
__global__ __launch_bounds__(256, 2) void xproj_kernel(
    const float* __restrict__ x,
    const float* __restrict__ bf, const float* __restrict__ bi,
    const float* __restrict__ bc, const float* __restrict__ bo)
{
    __shared__ float As[2][128][20];
    __shared__ float Bs[2][128][20];
    const int tid = threadIdx.x, lane = tid & 31, warp = tid >> 5;
    const int wm = warp >> 1, wn = warp & 1;
    const int gq = lane >> 2, tq = lane & 3;
    const int m0 = blockIdx.y * 128, n0 = blockIdx.x * 128;

    float acc[2][8][4];
    #pragma unroll
    for (int a = 0; a < 2; a++)
        #pragma unroll
        for (int b = 0; b < 8; b++)
            #pragma unroll
            for (int c = 0; c < 4; c++) acc[a][b][c] = 0.f;

    float4 ra[2], rb[2];
    #pragma unroll
    for (int it = 0; it < 2; it++) {
        int idx = tid + it * 256, row = idx >> 2, kq = idx & 3;
        ra[it] = *(const float4*)(x    + (size_t)(m0 + row) * II + kq * 4);
        rb[it] = *(const float4*)(g_Up + (size_t)(n0 + row) * II + kq * 4);
    }
    #pragma unroll
    for (int it = 0; it < 2; it++) {
        int idx = tid + it * 256, row = idx >> 2, kq = idx & 3;
        As[0][row][kq*4+0] = tf32r(ra[it].x); As[0][row][kq*4+1] = tf32r(ra[it].y);
        As[0][row][kq*4+2] = tf32r(ra[it].z); As[0][row][kq*4+3] = tf32r(ra[it].w);
        Bs[0][row][kq*4+0] = rb[it].x; Bs[0][row][kq*4+1] = rb[it].y;
        Bs[0][row][kq*4+2] = rb[it].z; Bs[0][row][kq*4+3] = rb[it].w;
    }
    __syncthreads();

    const int NK = II / 16;
    for (int kc = 0; kc < NK; kc++) {
        int buf = kc & 1;
        if (kc + 1 < NK) {
            int k0 = (kc + 1) * 16;
            #pragma unroll
            for (int it = 0; it < 2; it++) {
                int idx = tid + it * 256, row = idx >> 2, kq = idx & 3;
                ra[it] = *(const float4*)(x    + (size_t)(m0 + row) * II + k0 + kq * 4);
                rb[it] = *(const float4*)(g_Up + (size_t)(n0 + row) * II + k0 + kq * 4);
            }
        }
        #pragma unroll
        for (int kk = 0; kk < 16; kk += 8) {
            unsigned a[2][4], b[8][2];
            #pragma unroll
            for (int mf = 0; mf < 2; mf++) {
                int r = wm * 32 + mf * 16 + gq;
                a[mf][0] = __float_as_uint(As[buf][r    ][kk + tq]);
                a[mf][1] = __float_as_uint(As[buf][r + 8][kk + tq]);
                a[mf][2] = __float_as_uint(As[buf][r    ][kk + tq + 4]);
                a[mf][3] = __float_as_uint(As[buf][r + 8][kk + tq + 4]);
            }
            #pragma unroll
            for (int nf = 0; nf < 8; nf++) {
                int c = wn * 64 + nf * 8 + gq;
                b[nf][0] = __float_as_uint(Bs[buf][c][kk + tq]);
                b[nf][1] = __float_as_uint(Bs[buf][c][kk + tq + 4]);
            }
            #pragma unroll
            for (int mf = 0; mf < 2; mf++)
                #pragma unroll
                for (int nf = 0; nf < 8; nf++)
                    mma8(acc[mf][nf], a[mf], b[nf]);
        }
        if (kc + 1 < NK) {
            int nb = buf ^ 1;
            #pragma unroll
            for (int it = 0; it < 2; it++) {
                int idx = tid + it * 256, row = idx >> 2, kq = idx & 3;
                As[nb][row][kq*4+0] = tf32r(ra[it].x); As[nb][row][kq*4+1] = tf32r(ra[it].y);
                As[nb][row][kq*4+2] = tf32r(ra[it].z); As[nb][row][kq*4+3] = tf32r(ra[it].w);
                Bs[nb][row][kq*4+0] = rb[it].x; Bs[nb][row][kq*4+1] = rb[it].y;
                Bs[nb][row][kq*4+2] = rb[it].z; Bs[nb][row][kq*4+3] = rb[it].w;
            }
        }
        __syncthreads();
    }

    #pragma unroll
    for (int mf = 0; mf < 2; mf++) {
        int mr = m0 + wm * 32 + mf * 16 + gq;
        int m1 = mr + 8;
        size_t r0 = (size_t)(((mr & 511) << 6) | (mr >> 9)) * NG;
        size_t r1 = (size_t)(((m1 & 511) << 6) | (m1 >> 9)) * NG;
        #pragma unroll
        for (int nf = 0; nf < 8; nf++) {
            int c0 = n0 + wn * 64 + nf * 8 + 2 * tq;
            int gate = c0 >> 10;
            const float* bp = (gate == 0) ? bf : (gate == 1) ? bi : (gate == 2) ? bc : bo;
            float bv0 = bp[c0 & 1023], bv1 = bp[(c0 + 1) & 1023];
            g_xp[r0 + c0    ] = acc[mf][nf][0] + bv0;
            g_xp[r0 + c0 + 1] = acc[mf][nf][1] + bv1;
            g_xp[r1 + c0    ] = acc[mf][nf][2] + bv0;
            g_xp[r1 + c0 + 1] = acc[mf][nf][3] + bv1;
        }
    }
}

// ---------------- persistent recurrence kernel ----------------
// 128 CTAs x 256 thr (8 warps). CTA j owns hidden cols [8j,8j+8) -> 32 gate cols.
// W slice resident in SMEM in b-fragment layout (one LDS64 per fragment).
// Warps: wm = w&3 (16-row slab), kh = w>>2 (K half, split-K=2).
// SMEM: Wsm 128KB | As[kh][buf][64][36] 36KB | red 8KB  = 176128 B
#define SM_W_BYTES   131072
#define SM_AS_BYTES  36864
#define SM_RED_BYTES 8192
#define SM_TOTAL     (SM_W_BYTES + SM_AS_BYTES + SM_RED_BYTES)

__global__ __launch_bounds__(PTHR, 1) void lstm_persistent(float* __restrict__ out_hs)
{
    extern __shared__ __align__(16) unsigned char sm_raw[];
    float2* Wsm = (float2*)sm_raw;                                   // 16384 float2
    float (*As)[2][64][36] = (float (*)[2][64][36])(sm_raw + SM_W_BYTES);
    float4* red = (float4*)(sm_raw + SM_W_BYTES + SM_AS_BYTES);      // 512 float4

    const int tid = threadIdx.x;
    const int lane = tid & 31, w = tid >> 5;
    const int wm = w & 3, kh = w >> 2;
    const int gq = lane >> 2, tq = lane & 3;
    const int j = blockIdx.x;

    // ---- one-time: load W slice into fragment layout ----
    // Wsm[((kk8*4 + g)*8 + gq)*4 + tq] = { W^T[n][8kk8+tq], W^T[n][8kk8+tq+4] },
    // n = g*1024 + j*8 + gq   (matches proven b-frag mapping)
    #pragma unroll
    for (int t = 0; t < 16; t++) {
        int job = tid + t * PTHR;        // 4096 jobs = 32 n x 128 kk8
        int n = job >> 7;
        int kk8 = job & 127;
        int g = n >> 3, gn = n & 7;
        const float* src = g_Wp + (size_t)(g * 1024 + j * 8 + gn) * HH + kk8 * 8;
        float4 lo = *(const float4*)src;
        float4 hi = *(const float4*)(src + 4);
        float2* dst = Wsm + (size_t)((kk8 * 4 + g) * 8 + gn) * 4;
        dst[0] = make_float2(lo.x, hi.x);
        dst[1] = make_float2(lo.y, hi.y);
        dst[2] = make_float2(lo.z, hi.z);
        dst[3] = make_float2(lo.w, hi.w);
    }
    __syncthreads();

    unsigned gen = 0;

    for (int s = 0; s < SS; s++) {
        const float* __restrict__ h_old = g_h[s & 1];
        float* __restrict__ h_new = g_h[(s + 1) & 1];

        float acc[4][4];
        #pragma unroll
        for (int g = 0; g < 4; g++)
            #pragma unroll
            for (int p = 0; p < 4; p++) acc[g][p] = 0.f;

        // stage chunk 0 (both K halves), L2-only loads (L1 not coherent here)
        float4 ra[2][2];
        #pragma unroll
        for (int k2 = 0; k2 < 2; k2++)
            #pragma unroll
            for (int it = 0; it < 2; it++) {
                int idx = tid + it * PTHR;
                int row = idx >> 3, k4 = idx & 7;
                ra[k2][it] = __ldcg((const float4*)(h_old + (size_t)row * HH + k2 * 512 + k4 * 4));
            }
        #pragma unroll
        for (int k2 = 0; k2 < 2; k2++)
            #pragma unroll
            for (int it = 0; it < 2; it++) {
                int idx = tid + it * PTHR;
                int row = idx >> 3, k4 = idx & 7;
                float4 v = make_float4(tf32r(ra[k2][it].x), tf32r(ra[k2][it].y),
                                       tf32r(ra[k2][it].z), tf32r(ra[k2][it].w));
                *(float4*)&As[k2][0][row][k4 * 4] = v;
            }
        __syncthreads();

        const int NKC = 16;                     // 16 chunks of 32 k per half
        for (int kc = 0; kc < NKC; kc++) {
            int buf = kc & 1;
            if (kc + 1 < NKC) {
                int kb = (kc + 1) * 32;
                #pragma unroll
                for (int k2 = 0; k2 < 2; k2++)
                    #pragma unroll
                    for (int it = 0; it < 2; it++) {
                        int idx = tid + it * PTHR;
                        int row = idx >> 3, k4 = idx & 7;
                        ra[k2][it] = __ldcg((const float4*)(h_old + (size_t)row * HH +
                                                            k2 * 512 + kb + k4 * 4));
                    }
            }
            // compute: warp (wm, kh) -> rows [16wm,16wm+16), k in its half
            #pragma unroll
            for (int kk4 = 0; kk4 < 4; kk4++) {
                int kk = kk4 * 8;
                unsigned a[4];
                int r = wm * 16 + gq;
                a[0] = __float_as_uint(As[kh][buf][r    ][kk + tq]);
                a[1] = __float_as_uint(As[kh][buf][r + 8][kk + tq]);
                a[2] = __float_as_uint(As[kh][buf][r    ][kk + tq + 4]);
                a[3] = __float_as_uint(As[kh][buf][r + 8][kk + tq + 4]);
                int kk8 = kh * 64 + kc * 4 + kk4;
                #pragma unroll
                for (int g = 0; g < 4; g++) {
                    float2 bv = Wsm[(size_t)((kk8 * 4 + g) * 8 + gq) * 4 + tq];
                    unsigned b[2] = { __float_as_uint(bv.x), __float_as_uint(bv.y) };
                    mma8(acc[g], a, b);
                }
            }
            if (kc + 1 < NKC) {
                int nb = buf ^ 1;
                #pragma unroll
                for (int k2 = 0; k2 < 2; k2++)
                    #pragma unroll
                    for (int it = 0; it < 2; it++) {
                        int idx = tid + it * PTHR;
                        int row = idx >> 3, k4 = idx & 7;
                        float4 v = make_float4(tf32r(ra[k2][it].x), tf32r(ra[k2][it].y),
                                               tf32r(ra[k2][it].z), tf32r(ra[k2][it].w));
                        *(float4*)&As[k2][nb][row][k4 * 4] = v;
                    }
                __syncthreads();
            }
        }

        // split-K reduction: kh=1 warps dump partials, kh=0 warps combine
        if (kh == 1) {
            float4* dst = red + (wm * 32 + lane) * 4;
            #pragma unroll
            for (int g = 0; g < 4; g++)
                dst[g] = make_float4(acc[g][0], acc[g][1], acc[g][2], acc[g][3]);
        }
        __syncthreads();

        if (kh == 0) {
            float4* srcr = red + (wm * 32 + lane) * 4;
            #pragma unroll
            for (int g = 0; g < 4; g++) {
                float4 v = srcr[g];
                acc[g][0] += v.x; acc[g][1] += v.y; acc[g][2] += v.z; acc[g][3] += v.w;
            }
            // fused gate epilogue
            const float* __restrict__ xp = g_xp + (size_t)(s * 64) * NG;
            #pragma unroll
            for (int q = 0; q < 2; q++) {
                int brow = wm * 16 + gq + 8 * q;
                int col  = j * 8 + 2 * tq;
                size_t xo = (size_t)brow * NG + col;
                float2 xf = *(const float2*)(xp + xo);
                float2 xi = *(const float2*)(xp + xo + 1024);
                float2 xc = *(const float2*)(xp + xo + 2048);
                float2 xg = *(const float2*)(xp + xo + 3072);
                float gf0 = acc[0][2*q] + xf.x, gf1 = acc[0][2*q+1] + xf.y;
                float gi0 = acc[1][2*q] + xi.x, gi1 = acc[1][2*q+1] + xi.y;
                float gc0 = acc[2][2*q] + xc.x, gc1 = acc[2][2*q+1] + xc.y;
                float go0 = acc[3][2*q] + xg.x, go1 = acc[3][2*q+1] + xg.y;
                int ci = brow * HH + col;
                float2 cold = *(const float2*)(g_c + ci);
                float cn0 = sigmf(gf0) * cold.x + sigmf(gi0) * tanhf(gc0);
                float cn1 = sigmf(gf1) * cold.y + sigmf(gi1) * tanhf(gc1);
                *(float2*)(g_c + ci) = make_float2(cn0, cn1);
                float hn0 = sigmf(go0) * tanhf(cn0);
                float hn1 = sigmf(go1) * tanhf(cn1);
                __stcg((float2*)(h_new + ci), make_float2(hn0, hn1));
                *(float2*)(out_hs + ((size_t)brow * SS + s) * HH + col) = make_float2(hn0, hn1);
            }
        }

        // grid barrier (release h_new writes, acquire peers')
        __threadfence();
        __syncthreads();
        gen++;
        if (tid == 0) {
            unsigned t = atomicAdd(&g_cnt, 1u);
            if (t == gen * NCTA - 1u) {
                atomicExch(&g_gen, gen);
            } else {
                while (atomicAdd(&g_gen, 0u) < gen) { }
            }
            __threadfence();
        }
        __syncthreads();
    }
}

__global__ void final_kernel(float* __restrict__ out) {
    int i = blockIdx.x * blockDim.x + threadIdx.x;
    if (i < BB * HH) {
        out[i] = g_h[0][i];           // h_T (512 steps -> parity 0)
        out[BB * HH + i] = g_c[i];    // c_T
    }
}

// ---------------- launch ----------------
extern "C" void kernel_launch(void* const* d_in, const int* in_sizes, int n_in,
                              void* d_out, int out_size)
{
    const float* x  = (const float*)d_in[0];
    const float* Uf = (const float*)d_in[1];
    const float* Ui = (const float*)d_in[2];
    const float* Uc = (const float*)d_in[3];
    const float* Uo = (const float*)d_in[4];
    const float* Wf = (const float*)d_in[5];
    const float* Wi = (const float*)d_in[6];
    const float* Wc = (const float*)d_in[7];
    const float* Wo = (const float*)d_in[8];
    const float* bf = (const float*)d_in[9];
    const float* bi = (const float*)d_in[10];
    const float* bc = (const float*)d_in[11];
    const float* bo = (const float*)d_in[12];
    float* out = (float*)d_out;

    static int smem_set = 0;
    if (!smem_set) {
        cudaFuncSetAttribute(lstm_persistent,
                             cudaFuncAttributeMaxDynamicSharedMemorySize, SM_TOTAL);
        smem_set = 1;
    }

    pack_kernel<<<dim3(32, 32, 8), dim3(32, 8)>>>(Uf, Ui, Uc, Uo, Wf, Wi, Wc, Wo);
    init_kernel<<<(BB * HH + 255) / 256, 256>>>();
    xproj_kernel<<<dim3(NG / 128, MMR / 128), 256>>>(x, bf, bi, bc, bo);

    float* hs = out + 2 * BB * HH;   // hidden_seq region
    lstm_persistent<<<NCTA, PTHR, SM_TOTAL>>>(hs);

    final_kernel<<<(BB * HH + 255) / 256, 256>>>(out);
}

// round 6
// speedup vs baseline: 2.1522x; 1.4649x over previous
#include <cuda_runtime.h>

#define BB 64
#define SS 512
#define II 1024
#define HH 1024
#define NG 4096          // 4*H
#define MMR (BB*SS)      // 32768
#define NCTA 128
#define PTHR 512

// ---------------- device scratch (no allocs allowed) ----------------
__device__ __align__(16) float g_Up[(size_t)NG * II];       // U_all^T  [n][k], tf32-rounded
__device__ __align__(16) float g_Wp[(size_t)NG * HH];       // W_all^T  [n][k], tf32-rounded
__device__ __align__(16) float g_xp[(size_t)MMR * NG];      // x_proj   [(s*64+b)][4H]
// h in a-fragment order: [buf][kk8(128)][row(64)][q(4) as float2 {k=8kk8+q, k=8kk8+q+4}]
__device__ __align__(16) float g_hf[2][64 * 1024];
__device__ unsigned g_cnt;                                   // grid barrier arrivals
__device__ unsigned g_gen;                                   // grid barrier generation

// ---------------- helpers ----------------
__device__ __forceinline__ float tf32r(float f) {
    unsigned u;
    asm("cvt.rna.tf32.f32 %0, %1;" : "=r"(u) : "f"(f));
    return __uint_as_float(u);
}

__device__ __forceinline__ void mma8(float* d, const unsigned* a, const unsigned* b) {
    asm volatile(
        "mma.sync.aligned.m16n8k8.row.col.f32.tf32.tf32.f32 "
        "{%0,%1,%2,%3}, {%4,%5,%6,%7}, {%8,%9}, {%0,%1,%2,%3};"
        : "+f"(d[0]), "+f"(d[1]), "+f"(d[2]), "+f"(d[3])
        : "r"(a[0]), "r"(a[1]), "r"(a[2]), "r"(a[3]), "r"(b[0]), "r"(b[1]));
}

__device__ __forceinline__ float sigmf(float x) { return 1.f / (1.f + __expf(-x)); }

// ---------------- pack: build K-major tf32 U_all^T / W_all^T ----------------
__global__ void pack_kernel(
    const float* __restrict__ Uf, const float* __restrict__ Ui,
    const float* __restrict__ Uc, const float* __restrict__ Uo,
    const float* __restrict__ Wf, const float* __restrict__ Wi,
    const float* __restrict__ Wc, const float* __restrict__ Wo)
{
    __shared__ float t[32][33];
    int z = blockIdx.z;
    int g = z & 3;
    const float* src;
    float* dst;
    if (z < 4) { src = (g == 0) ? Uf : (g == 1) ? Ui : (g == 2) ? Uc : Uo; dst = g_Up; }
    else       { src = (g == 0) ? Wf : (g == 1) ? Wi : (g == 2) ? Wc : Wo; dst = g_Wp; }
    int n0 = blockIdx.x * 32, k0 = blockIdx.y * 32;
    int tx = threadIdx.x, ty = threadIdx.y;   // 32 x 8
    #pragma unroll
    for (int i = 0; i < 4; i++) {
        int kr = ty + i * 8;
        t[kr][tx] = src[(size_t)(k0 + kr) * HH + n0 + tx];
    }
    __syncthreads();
    #pragma unroll
    for (int i = 0; i < 4; i++) {
        int nr = ty + i * 8;
        dst[(size_t)(g * HH + n0 + nr) * II + k0 + tx] = tf32r(t[tx][nr]);
    }
}

__global__ void init_kernel() {
    int i = blockIdx.x * blockDim.x + threadIdx.x;
    if (i < 64 * 1024) g_hf[0][i] = 0.f;
    if (i == 0) { g_cnt = 0u; g_gen = 0u; }
}

// ---------------- phase 1: x_proj = x @ U_all + b ----------------
__global__ __launch_bounds__(256, 2) void xproj_kernel(
    const float* __restrict__ x,
    const float* __restrict__ bf, const float* __restrict__ bi,
    const float* __restrict__ bc, const float* __restrict__ bo)
{
    __shared__ float As[2][128][20];
    __shared__ float Bs[2][128][20];
    const int tid = threadIdx.x, lane = tid & 31, warp = tid >> 5;
    const int wm = warp >> 1, wn = warp & 1;
    const int gq = lane >> 2, tq = lane & 3;
    const int m0 = blockIdx.y * 128, n0 = blockIdx.x * 128;

    float acc[2][8][4];
    #pragma unroll
    for (int a = 0; a < 2; a++)
        #pragma unroll
        for (int b = 0; b < 8; b++)
            #pragma unroll
            for (int c = 0; c < 4; c++) acc[a][b][c] = 0.f;

    float4 ra[2], rb[2];
    #pragma unroll
    for (int it = 0; it < 2; it++) {
        int idx = tid + it * 256, row = idx >> 2, kq = idx & 3;
        ra[it] = *(const float4*)(x    + (size_t)(m0 + row) * II + kq * 4);
        rb[it] = *(const float4*)(g_Up + (size_t)(n0 + row) * II + kq * 4);
    }
    #pragma unroll
    for (int it = 0; it < 2; it++) {
        int idx = tid + it * 256, row = idx >> 2, kq = idx & 3;
        As[0][row][kq*4+0] = tf32r(ra[it].x); As[0][row][kq*4+1] = tf32r(ra[it].y);
        As[0][row][kq*4+2] = tf32r(ra[it].z); As[0][row][kq*4+3] = tf32r(ra[it].w);
        Bs[0][row][kq*4+0] = rb[it].x; Bs[0][row][kq*4+1] = rb[it].y;
        Bs[0][row][kq*4+2] = rb[it].z; Bs[0][row][kq*4+3] = rb[it].w;
    }
    __syncthreads();

    const int NK = II / 16;
    for (int kc = 0; kc < NK; kc++) {
        int buf = kc & 1;
        if (kc + 1 < NK) {
            int k0 = (kc + 1) * 16;
            #pragma unroll
            for (int it = 0; it < 2; it++) {
                int idx = tid + it * 256, row = idx >> 2, kq = idx & 3;
                ra[it] = *(const float4*)(x    + (size_t)(m0 + row) * II + k0 + kq * 4);
                rb[it] = *(const float4*)(g_Up + (size_t)(n0 + row) * II + k0 + kq * 4);
            }
        }
        #pragma unroll
        for (int kk = 0; kk < 16; kk += 8) {
            unsigned a[2][4], b[8][2];
            #pragma unroll
            for (int mf = 0; mf < 2; mf++) {
                int r = wm * 32 + mf * 16 + gq;
                a[mf][0] = __float_as_uint(As[buf][r    ][kk + tq]);
                a[mf][1] = __float_as_uint(As[buf][r + 8][kk + tq]);
                a[mf][2] = __float_as_uint(As[buf][r    ][kk + tq + 4]);
                a[mf][3] = __float_as_uint(As[buf][r + 8][kk + tq + 4]);
            }
            #pragma unroll
            for (int nf = 0; nf < 8; nf++) {
                int c = wn * 64 + nf * 8 + gq;
                b[nf][0] = __float_as_uint(Bs[buf][c][kk + tq]);
                b[nf][1] = __float_as_uint(Bs[buf][c][kk + tq + 4]);
            }
            #pragma unroll
            for (int mf = 0; mf < 2; mf++)
                #pragma unroll
                for (int nf = 0; nf < 8; nf++)
                    mma8(acc[mf][nf], a[mf], b[nf]);
        }
        if (kc + 1 < NK) {
            int nb = buf ^ 1;
            #pragma unroll
            for (int it = 0; it < 2; it++) {
                int idx = tid + it * 256, row = idx >> 2, kq = idx & 3;
                As[nb][row][kq*4+0] = tf32r(ra[it].x); As[nb][row][kq*4+1] = tf32r(ra[it].y);
                As[nb][row][kq*4+2] = tf32r(ra[it].z); As[nb][row][kq*4+3] = tf32r(ra[it].w);
                Bs[nb][row][kq*4+0] = rb[it].x; Bs[nb][row][kq*4+1] = rb[it].y;
                Bs[nb][row][kq*4+2] = rb[it].z; Bs[nb][row][kq*4+3] = rb[it].w;
            }
        }
        __syncthreads();
    }

    #pragma unroll
    for (int mf = 0; mf < 2; mf++) {
        int mr = m0 + wm * 32 + mf * 16 + gq;
        int m1 = mr + 8;
        size_t r0 = (size_t)(((mr & 511) << 6) | (mr >> 9)) * NG;
        size_t r1 = (size_t)(((m1 & 511) << 6) | (m1 >> 9)) * NG;
        #pragma unroll
        for (int nf = 0; nf < 8; nf++) {
            int c0 = n0 + wn * 64 + nf * 8 + 2 * tq;
            int gate = c0 >> 10;
            const float* bp = (gate == 0) ? bf : (gate == 1) ? bi : (gate == 2) ? bc : bo;
            float bv0 = bp[c0 & 1023], bv1 = bp[(c0 + 1) & 1023];
            g_xp[r0 + c0    ] = acc[mf][nf][0] + bv0;
            g_xp[r0 + c0 + 1] = acc[mf][nf][1] + bv1;
            g_xp[r1 + c0    ] = acc[mf][nf][2] + bv0;
            g_xp[r1 + c0 + 1] = acc[mf][nf][3] + bv1;
        }
    }
}

// ---------------- persistent recurrence kernel ----------------
// 128 CTAs x 512 thr (16 warps). CTA j owns hidden cols [8j,8j+8) -> 32 gate cols.
// Warps: wm = w&3 (16-row slab), kh = w>>2 (K quarter, split-K=4).
// h lives in GLOBAL memory in a-fragment order (g_hf) -> coalesced LDG.64, no smem staging.
// W fragments SMEM-resident (128KB). One __syncthreads per step + grid barrier.
#define SM_W_BYTES   131072
#define SM_RED_BYTES 24576          // 3 slots x 128 thr x 4 gates x float4
#define SM_TOTAL     (SM_W_BYTES + SM_RED_BYTES)

__global__ __launch_bounds__(PTHR, 1) void lstm_persistent(
    float* __restrict__ out, float* __restrict__ out_hs)
{
    extern __shared__ __align__(16) unsigned char sm_raw[];
    float2* Wsm = (float2*)sm_raw;                               // 16384 float2
    float4* red = (float4*)(sm_raw + SM_W_BYTES);                // [3][128][4] float4

    const int tid = threadIdx.x;
    const int lane = tid & 31, w = tid >> 5;
    const int wm = w & 3, kh = w >> 2;        // kh in [0,4)
    const int gq = lane >> 2, tq = lane & 3;
    const int j = blockIdx.x;

    // ---- one-time: load W slice into fragment layout ----
    // Wsm[((kk8*4 + g)*8 + gq)*4 + tq] = { W^T[n][8kk8+tq], W^T[n][8kk8+tq+4] },
    // n = g*1024 + j*8 + gq
    #pragma unroll
    for (int t = 0; t < 8; t++) {
        int job = tid + t * PTHR;        // 4096 jobs = 32 n x 128 kk8
        int n = job >> 7;
        int kk8 = job & 127;
        int g = n >> 3, gn = n & 7;
        const float* src = g_Wp + (size_t)(g * 1024 + j * 8 + gn) * HH + kk8 * 8;
        float4 lo = *(const float4*)src;
        float4 hi = *(const float4*)(src + 4);
        float2* dst = Wsm + (size_t)((kk8 * 4 + g) * 8 + gn) * 4;
        dst[0] = make_float2(lo.x, hi.x);
        dst[1] = make_float2(lo.y, hi.y);
        dst[2] = make_float2(lo.z, hi.z);
        dst[3] = make_float2(lo.w, hi.w);
    }
    __syncthreads();

    // persistent per-thread cell state (kh==0 threads only use it)
    float creg[2][2] = {{0.f, 0.f}, {0.f, 0.f}};
    unsigned gen = 0;

    const int kbase = kh * 32;       // this warp's kk8 range: [kbase, kbase+32)
    const int arow_lo = wm * 16 + gq;          // a-frag rows
    const int colg = j * 8 + 2 * tq;           // output cols (kh==0 epilogue)

    for (int s = 0; s < SS; s++) {
        const float2* __restrict__ hb = (const float2*)g_hf[s & 1];
        float*        __restrict__ hw = g_hf[(s + 1) & 1];

        // prefetch xp for epilogue (kh==0 only): [q'][gate]
        float2 xf[2][4];
        if (kh == 0) {
            const float* xp = g_xp + (size_t)(s * 64) * NG;
            #pragma unroll
            for (int q = 0; q < 2; q++) {
                int brow = arow_lo + 8 * q;
                #pragma unroll
                for (int g = 0; g < 4; g++)
                    xf[q][g] = __ldg((const float2*)(xp + (size_t)brow * NG + g * 1024 + colg));
            }
        }

        float acc[4][4];
        #pragma unroll
        for (int g = 0; g < 4; g++)
            #pragma unroll
            for (int p = 0; p < 4; p++) acc[g][p] = 0.f;

        // 8-deep a-fragment prefetch queue (coalesced 256B LDG.64s from L2)
        float2 qlo[8], qhi[8];
        #pragma unroll
        for (int p = 0; p < 8; p++) {
            int idx = ((kbase + p) * 64 + arow_lo) * 4 + tq;
            qlo[p] = __ldcg(hb + idx);
            qhi[p] = __ldcg(hb + idx + 32);   // +8 rows
        }

        #pragma unroll 8
        for (int i = 0; i < 32; i++) {
            int sl = i & 7;
            float2 lo = qlo[sl], hi = qhi[sl];
            if (i < 24) {
                int idx = ((kbase + i + 8) * 64 + arow_lo) * 4 + tq;
                qlo[sl] = __ldcg(hb + idx);
                qhi[sl] = __ldcg(hb + idx + 32);
            }
            unsigned a[4] = { __float_as_uint(lo.x), __float_as_uint(hi.x),
                              __float_as_uint(lo.y), __float_as_uint(hi.y) };
            int kk8 = kbase + i;
            #pragma unroll
            for (int g = 0; g < 4; g++) {
                float2 bv = Wsm[(size_t)((kk8 * 4 + g) * 8 + gq) * 4 + tq];
                unsigned b[2] = { __float_as_uint(bv.x), __float_as_uint(bv.y) };
                mma8(acc[g], a, b);
            }
        }

        // split-K reduction: kh=1..3 dump partials, kh=0 combines
        if (kh != 0) {
            float4* dst = red + ((size_t)(kh - 1) * 128 + wm * 32 + lane) * 4;
            #pragma unroll
            for (int g = 0; g < 4; g++)
                dst[g] = make_float4(acc[g][0], acc[g][1], acc[g][2], acc[g][3]);
        }
        __syncthreads();

        if (kh == 0) {
            #pragma unroll
            for (int sl = 0; sl < 3; sl++) {
                float4* srcr = red + ((size_t)sl * 128 + wm * 32 + lane) * 4;
                #pragma unroll
                for (int g = 0; g < 4; g++) {
                    float4 v = srcr[g];
                    acc[g][0] += v.x; acc[g][1] += v.y; acc[g][2] += v.z; acc[g][3] += v.w;
                }
            }
            // fused gate epilogue; write h_new in fragment order (tf32-rounded)
            const int q0 = (2 * tq) & 3;      // fragment q index for col pair
            const int hf = tq >> 1;           // float2 half (0=.x, 1=.y)
            #pragma unroll
            for (int q = 0; q < 2; q++) {
                int brow = arow_lo + 8 * q;
                float gf0 = acc[0][2*q] + xf[q][0].x, gf1 = acc[0][2*q+1] + xf[q][0].y;
                float gi0 = acc[1][2*q] + xf[q][1].x, gi1 = acc[1][2*q+1] + xf[q][1].y;
                float gc0 = acc[2][2*q] + xf[q][2].x, gc1 = acc[2][2*q+1] + xf[q][2].y;
                float go0 = acc[3][2*q] + xf[q][3].x, go1 = acc[3][2*q+1] + xf[q][3].y;
                float cn0 = sigmf(gf0) * creg[q][0] + sigmf(gi0) * tanhf(gc0);
                float cn1 = sigmf(gf1) * creg[q][1] + sigmf(gi1) * tanhf(gc1);
                creg[q][0] = cn0; creg[q][1] = cn1;
                float hn0 = sigmf(go0) * tanhf(cn0);
                float hn1 = sigmf(go1) * tanhf(cn1);
                // fragment-order h write: row = (j*64 + brow), 8 floats/row
                float* hrow = hw + (size_t)(j * 64 + brow) * 8;
                __stcg(hrow + q0 * 2 + hf,       tf32r(hn0));
                __stcg(hrow + (q0 + 1) * 2 + hf, tf32r(hn1));
                // hidden_seq (B,S,H), full precision
                *(float2*)(out_hs + ((size_t)brow * SS + s) * HH + colg) = make_float2(hn0, hn1);
                if (s == SS - 1) {
                    out[(size_t)brow * HH + colg]     = hn0;
                    out[(size_t)brow * HH + colg + 1] = hn1;
                    out[(size_t)BB * HH + brow * HH + colg]     = cn0;
                    out[(size_t)BB * HH + brow * HH + colg + 1] = cn1;
                }
            }
        }

        // grid barrier (release h_new writes, acquire peers')
        __threadfence();
        __syncthreads();
        gen++;
        if (tid == 0) {
            unsigned t = atomicAdd(&g_cnt, 1u);
            if (t == gen * NCTA - 1u) {
                atomicExch(&g_gen, gen);
            } else {
                unsigned v;
                do {
                    asm volatile("ld.acquire.gpu.global.u32 %0, [%1];"
                                 : "=r"(v) : "l"(&g_gen) : "memory");
                } while (v < gen);
            }
            __threadfence();
        }
        __syncthreads();
    }
}

// ---------------- launch ----------------
extern "C" void kernel_launch(void* const* d_in, const int* in_sizes, int n_in,
                              void* d_out, int out_size)
{
    const float* x  = (const float*)d_in[0];
    const float* Uf = (const float*)d_in[1];
    const float* Ui = (const float*)d_in[2];
    const float* Uc = (const float*)d_in[3];
    const float* Uo = (const float*)d_in[4];
    const float* Wf = (const float*)d_in[5];
    const float* Wi = (const float*)d_in[6];
    const float* Wc = (const float*)d_in[7];
    const float* Wo = (const float*)d_in[8];
    const float* bf = (const float*)d_in[9];
    const float* bi = (const float*)d_in[10];
    const float* bc = (const float*)d_in[11];
    const float* bo = (const float*)d_in[12];
    float* out = (float*)d_out;

    static int smem_set = 0;
    if (!smem_set) {
        cudaFuncSetAttribute(lstm_persistent,
                             cudaFuncAttributeMaxDynamicSharedMemorySize, SM_TOTAL);
        smem_set = 1;
    }

    pack_kernel<<<dim3(32, 32, 8), dim3(32, 8)>>>(Uf, Ui, Uc, Uo, Wf, Wi, Wc, Wo);
    init_kernel<<<(64 * 1024 + 255) / 256, 256>>>();
    xproj_kernel<<<dim3(NG / 128, MMR / 128), 256>>>(x, bf, bi, bc, bo);

    float* hs = out + 2 * BB * HH;   // hidden_seq region
    lstm_persistent<<<NCTA, PTHR, SM_TOTAL>>>(out, hs);
}

// round 7
// speedup vs baseline: 2.2363x; 1.0390x over previous
#include <cuda_runtime.h>

#define BB 64
#define SS 512
#define II 1024
#define HH 1024
#define NG 4096          // 4*H
#define MMR (BB*SS)      // 32768
#define NCTA 128
#define PTHR 512

// ---------------- device scratch (no allocs allowed) ----------------
__device__ __align__(16) float g_Up[(size_t)NG * II];       // U_all^T  [n][k], tf32-rounded
__device__ __align__(16) float g_Wp[(size_t)NG * HH];       // W_all^T  [n][k], tf32-rounded
__device__ __align__(16) float g_xp[(size_t)MMR * NG];      // x_proj   [(s*64+b)][4H]
// h in a-fragment order: [buf][kk8(128)][row(64)][q(4) as float2 {k=8kk8+q, k=8kk8+q+4}]
__device__ __align__(16) float g_hf[2][64 * 1024];
__device__ unsigned g_cnt;                                   // grid barrier arrivals
__device__ unsigned g_gen;                                   // grid barrier generation

// ---------------- helpers ----------------
__device__ __forceinline__ float tf32r(float f) {
    unsigned u;
    asm("cvt.rna.tf32.f32 %0, %1;" : "=r"(u) : "f"(f));
    return __uint_as_float(u);
}

__device__ __forceinline__ void mma8(float* d, const unsigned* a, unsigned b0, unsigned b1) {
    asm volatile(
        "mma.sync.aligned.m16n8k8.row.col.f32.tf32.tf32.f32 "
        "{%0,%1,%2,%3}, {%4,%5,%6,%7}, {%8,%9}, {%0,%1,%2,%3};"
        : "+f"(d[0]), "+f"(d[1]), "+f"(d[2]), "+f"(d[3])
        : "r"(a[0]), "r"(a[1]), "r"(a[2]), "r"(a[3]), "r"(b0), "r"(b1));
}

__device__ __forceinline__ float sigmf(float x) { return 1.f / (1.f + __expf(-x)); }

// ---------------- pack: build K-major tf32 U_all^T / W_all^T ----------------
__global__ void pack_kernel(
    const float* __restrict__ Uf, const float* __restrict__ Ui,
    const float* __restrict__ Uc, const float* __restrict__ Uo,
    const float* __restrict__ Wf, const float* __restrict__ Wi,
    const float* __restrict__ Wc, const float* __restrict__ Wo)
{
    __shared__ float t[32][33];
    int z = blockIdx.z;
    int g = z & 3;
    const float* src;
    float* dst;
    if (z < 4) { src = (g == 0) ? Uf : (g == 1) ? Ui : (g == 2) ? Uc : Uo; dst = g_Up; }
    else       { src = (g == 0) ? Wf : (g == 1) ? Wi : (g == 2) ? Wc : Wo; dst = g_Wp; }
    int n0 = blockIdx.x * 32, k0 = blockIdx.y * 32;
    int tx = threadIdx.x, ty = threadIdx.y;   // 32 x 8
    #pragma unroll
    for (int i = 0; i < 4; i++) {
        int kr = ty + i * 8;
        t[kr][tx] = src[(size_t)(k0 + kr) * HH + n0 + tx];
    }
    __syncthreads();
    #pragma unroll
    for (int i = 0; i < 4; i++) {
        int nr = ty + i * 8;
        dst[(size_t)(g * HH + n0 + nr) * II + k0 + tx] = tf32r(t[tx][nr]);
    }
}

__global__ void init_kernel() {
    int i = blockIdx.x * blockDim.x + threadIdx.x;
    if (i < 64 * 1024) g_hf[0][i] = 0.f;
    if (i == 0) { g_cnt = 0u; g_gen = 0u; }
}

// ---------------- phase 1: x_proj = x @ U_all + b ----------------
__global__ __launch_bounds__(256, 2) void xproj_kernel(
    const float* __restrict__ x,
    const float* __restrict__ bf, const float* __restrict__ bi,
    const float* __restrict__ bc, const float* __restrict__ bo)
{
    __shared__ float As[2][128][20];
    __shared__ float Bs[2][128][20];
    const int tid = threadIdx.x, lane = tid & 31, warp = tid >> 5;
    const int wm = warp >> 1, wn = warp & 1;
    const int gq = lane >> 2, tq = lane & 3;
    const int m0 = blockIdx.y * 128, n0 = blockIdx.x * 128;

    float acc[2][8][4];
    #pragma unroll
    for (int a = 0; a < 2; a++)
        #pragma unroll
        for (int b = 0; b < 8; b++)
            #pragma unroll
            for (int c = 0; c < 4; c++) acc[a][b][c] = 0.f;

    float4 ra[2], rb[2];
    #pragma unroll
    for (int it = 0; it < 2; it++) {
        int idx = tid + it * 256, row = idx >> 2, kq = idx & 3;
        ra[it] = *(const float4*)(x    + (size_t)(m0 + row) * II + kq * 4);
        rb[it] = *(const float4*)(g_Up + (size_t)(n0 + row) * II + kq * 4);
    }
    #pragma unroll
    for (int it = 0; it < 2; it++) {
        int idx = tid + it * 256, row = idx >> 2, kq = idx & 3;
        As[0][row][kq*4+0] = tf32r(ra[it].x); As[0][row][kq*4+1] = tf32r(ra[it].y);
        As[0][row][kq*4+2] = tf32r(ra[it].z); As[0][row][kq*4+3] = tf32r(ra[it].w);
        Bs[0][row][kq*4+0] = rb[it].x; Bs[0][row][kq*4+1] = rb[it].y;
        Bs[0][row][kq*4+2] = rb[it].z; Bs[0][row][kq*4+3] = rb[it].w;
    }
    __syncthreads();

    const int NK = II / 16;
    for (int kc = 0; kc < NK; kc++) {
        int buf = kc & 1;
        if (kc + 1 < NK) {
            int k0 = (kc + 1) * 16;
            #pragma unroll
            for (int it = 0; it < 2; it++) {
                int idx = tid + it * 256, row = idx >> 2, kq = idx & 3;
                ra[it] = *(const float4*)(x    + (size_t)(m0 + row) * II + k0 + kq * 4);
                rb[it] = *(const float4*)(g_Up + (size_t)(n0 + row) * II + k0 + kq * 4);
            }
        }
        #pragma unroll
        for (int kk = 0; kk < 16; kk += 8) {
            unsigned a[2][4], b[8][2];
            #pragma unroll
            for (int mf = 0; mf < 2; mf++) {
                int r = wm * 32 + mf * 16 + gq;
                a[mf][0] = __float_as_uint(As[buf][r    ][kk + tq]);
                a[mf][1] = __float_as_uint(As[buf][r + 8][kk + tq]);
                a[mf][2] = __float_as_uint(As[buf][r    ][kk + tq + 4]);
                a[mf][3] = __float_as_uint(As[buf][r + 8][kk + tq + 4]);
            }
            #pragma unroll
            for (int nf = 0; nf < 8; nf++) {
                int c = wn * 64 + nf * 8 + gq;
                b[nf][0] = __float_as_uint(Bs[buf][c][kk + tq]);
                b[nf][1] = __float_as_uint(Bs[buf][c][kk + tq + 4]);
            }
            #pragma unroll
            for (int mf = 0; mf < 2; mf++)
                #pragma unroll
                for (int nf = 0; nf < 8; nf++)
                    mma8(acc[mf][nf], a[mf], b[nf][0], b[nf][1]);
        }
        if (kc + 1 < NK) {
            int nb = buf ^ 1;
            #pragma unroll
            for (int it = 0; it < 2; it++) {
                int idx = tid + it * 256, row = idx >> 2, kq = idx & 3;
                As[nb][row][kq*4+0] = tf32r(ra[it].x); As[nb][row][kq*4+1] = tf32r(ra[it].y);
                As[nb][row][kq*4+2] = tf32r(ra[it].z); As[nb][row][kq*4+3] = tf32r(ra[it].w);
                Bs[nb][row][kq*4+0] = rb[it].x; Bs[nb][row][kq*4+1] = rb[it].y;
                Bs[nb][row][kq*4+2] = rb[it].z; Bs[nb][row][kq*4+3] = rb[it].w;
            }
        }
        __syncthreads();
    }

    #pragma unroll
    for (int mf = 0; mf < 2; mf++) {
        int mr = m0 + wm * 32 + mf * 16 + gq;
        int m1 = mr + 8;
        size_t r0 = (size_t)(((mr & 511) << 6) | (mr >> 9)) * NG;
        size_t r1 = (size_t)(((m1 & 511) << 6) | (m1 >> 9)) * NG;
        #pragma unroll
        for (int nf = 0; nf < 8; nf++) {
            int c0 = n0 + wn * 64 + nf * 8 + 2 * tq;
            int gate = c0 >> 10;
            const float* bp = (gate == 0) ? bf : (gate == 1) ? bi : (gate == 2) ? bc : bo;
            float bv0 = bp[c0 & 1023], bv1 = bp[(c0 + 1) & 1023];
            g_xp[r0 + c0    ] = acc[mf][nf][0] + bv0;
            g_xp[r0 + c0 + 1] = acc[mf][nf][1] + bv1;
            g_xp[r1 + c0    ] = acc[mf][nf][2] + bv0;
            g_xp[r1 + c0 + 1] = acc[mf][nf][3] + bv1;
        }
    }
}

// ---------------- persistent recurrence kernel ----------------
// 128 CTAs x 512 thr (16 warps = 2 m-slabs x 8 K-splits). CTA j owns hidden cols
// [8j,8j+8) -> 32 gate cols. W fragments in SMEM, gate-paired for LDS.128.
// h in global a-fragment order (g_hf). Unified 512-thread reduction+epilogue.
#define SM_W_BYTES   131072                    // 8192 float4
#define RED_STRIDE   36                        // floats per (warp,lane) slot, 16B aligned
#define SM_RED_BYTES (PTHR * RED_STRIDE * 4)   // 73728
#define SM_TOTAL     (SM_W_BYTES + SM_RED_BYTES)

__global__ __launch_bounds__(PTHR, 1) void lstm_persistent(
    float* __restrict__ out, float* __restrict__ out_hs)
{
    extern __shared__ __align__(16) unsigned char sm_raw[];
    float4* Wsm4 = (float4*)sm_raw;                          // [kk8][gp2][gq8][tq4]
    float2* Wsm2 = (float2*)sm_raw;
    float*  red  = (float*)(sm_raw + SM_W_BYTES);            // [(w*32+lane)*36 + mt*16 + g*4 + p]

    const int tid = threadIdx.x;
    const int lane = tid & 31, w = tid >> 5;
    const int wm = w & 1, kh = w >> 1;        // 2 m-slabs x 8 K-splits
    const int gq = lane >> 2, tq = lane & 3;
    const int j = blockIdx.x;

    // ---- one-time: load W slice into gate-paired fragment layout ----
    // Wsm4[((kk8*2+gp)*8 + gq)*4 + tq] = {W(2gp)[k=8kk8+tq], W(2gp)[+4], W(2gp+1)[tq], W(2gp+1)[+4]}
    // where W(g) is column n = g*1024 + j*8 + gq of W_all (row of g_Wp).
    #pragma unroll
    for (int t = 0; t < 8; t++) {
        int job = tid + t * PTHR;        // 4096 jobs = 32 n x 128 kk8
        int n = job >> 7;
        int kk8 = job & 127;
        int g = n >> 3, gn = n & 7;
        int gp = g >> 1, gh = g & 1;
        const float* src = g_Wp + (size_t)(g * 1024 + j * 8 + gn) * HH + kk8 * 8;
        float4 lo = *(const float4*)src;
        float4 hi = *(const float4*)(src + 4);
        int base2 = (((kk8 * 2 + gp) * 8 + gn) * 4) * 2;
        Wsm2[base2 + 0 * 2 + gh] = make_float2(lo.x, hi.x);
        Wsm2[base2 + 1 * 2 + gh] = make_float2(lo.y, hi.y);
        Wsm2[base2 + 2 * 2 + gh] = make_float2(lo.z, hi.z);
        Wsm2[base2 + 3 * 2 + gh] = make_float2(lo.w, hi.w);
    }
    __syncthreads();

    // ---- per-thread epilogue mapping (one (row, cc) output per thread) ----
    const int rrow = tid >> 3, cc = tid & 7;
    const int r_wm = rrow >> 5, r_mt = (rrow >> 4) & 1;
    const int r_p  = ((rrow >> 3) & 1) * 2 + (cc & 1);
    const int r_lane = (rrow & 7) * 4 + (cc >> 1);
    const int red_base = r_lane * RED_STRIDE + r_mt * 16 + r_p;   // + (kh2*2+r_wm)*32*RED_STRIDE + g*4
    const int colg = j * 8 + cc;
    const int hf_idx = (j * 64 + rrow) * 8 + (cc & 3) * 2 + (cc >> 2);

    float creg = 0.f;
    unsigned gen = 0;

    const int kbase = kh * 16;                 // this warp's kk8 range (16 slices)
    const int arow = wm * 32 + gq;             // mt0 a-frag row

    // prefetch xp for step 0
    float xr[4];
    #pragma unroll
    for (int g = 0; g < 4; g++)
        xr[g] = __ldg(g_xp + (size_t)rrow * NG + g * 1024 + colg);

    for (int s = 0; s < SS; s++) {
        const float2* __restrict__ hb = (const float2*)g_hf[s & 1];
        float*        __restrict__ hw = g_hf[(s + 1) & 1];

        float acc[2][4][4];
        #pragma unroll
        for (int mt = 0; mt < 2; mt++)
            #pragma unroll
            for (int g = 0; g < 4; g++)
                #pragma unroll
                for (int p = 0; p < 4; p++) acc[mt][g][p] = 0.f;

        // 4-deep a-fragment prefetch queue: [slot][lo0,hi0,lo1,hi1]
        float2 qA[4][4];
        #pragma unroll
        for (int p = 0; p < 4; p++) {
            int base = ((kbase + p) * 64 + arow) * 4 + tq;
            qA[p][0] = __ldcg(hb + base);
            qA[p][1] = __ldcg(hb + base + 32);    // +8 rows
            qA[p][2] = __ldcg(hb + base + 64);    // +16 rows (mt1)
            qA[p][3] = __ldcg(hb + base + 96);
        }

        #pragma unroll 4
        for (int i = 0; i < 16; i++) {
            int sl = i & 3;
            float2 l0 = qA[sl][0], h0 = qA[sl][1], l1 = qA[sl][2], h1 = qA[sl][3];
            if (i < 12) {
                int base = ((kbase + i + 4) * 64 + arow) * 4 + tq;
                qA[sl][0] = __ldcg(hb + base);
                qA[sl][1] = __ldcg(hb + base + 32);
                qA[sl][2] = __ldcg(hb + base + 64);
                qA[sl][3] = __ldcg(hb + base + 96);
            }
            unsigned a0[4] = { __float_as_uint(l0.x), __float_as_uint(h0.x),
                               __float_as_uint(l0.y), __float_as_uint(h0.y) };
            unsigned a1[4] = { __float_as_uint(l1.x), __float_as_uint(h1.x),
                               __float_as_uint(l1.y), __float_as_uint(h1.y) };
            int kk8 = kbase + i;
            float4 b01 = Wsm4[((kk8 * 2 + 0) * 8 + gq) * 4 + tq];
            float4 b23 = Wsm4[((kk8 * 2 + 1) * 8 + gq) * 4 + tq];
            mma8(acc[0][0], a0, __float_as_uint(b01.x), __float_as_uint(b01.y));
            mma8(acc[0][1], a0, __float_as_uint(b01.z), __float_as_uint(b01.w));
            mma8(acc[0][2], a0, __float_as_uint(b23.x), __float_as_uint(b23.y));
            mma8(acc[0][3], a0, __float_as_uint(b23.z), __float_as_uint(b23.w));
            mma8(acc[1][0], a1, __float_as_uint(b01.x), __float_as_uint(b01.y));
            mma8(acc[1][1], a1, __float_as_uint(b01.z), __float_as_uint(b01.w));
            mma8(acc[1][2], a1, __float_as_uint(b23.x), __float_as_uint(b23.y));
            mma8(acc[1][3], a1, __float_as_uint(b23.z), __float_as_uint(b23.w));
        }

        // dump all partials (16B-aligned float4 stores)
        {
            float* dst = red + (w * 32 + lane) * RED_STRIDE;
            #pragma unroll
            for (int mt = 0; mt < 2; mt++)
                #pragma unroll
                for (int g = 0; g < 4; g++)
                    *(float4*)(dst + mt * 16 + g * 4) =
                        make_float4(acc[mt][g][0], acc[mt][g][1], acc[mt][g][2], acc[mt][g][3]);
        }
        __syncthreads();

        // unified reduction + gate epilogue: one (row, cc) per thread
        {
            float gs[4];
            #pragma unroll
            for (int g = 0; g < 4; g++) {
                float v = 0.f;
                #pragma unroll
                for (int kh2 = 0; kh2 < 8; kh2++)
                    v += red[(kh2 * 2 + r_wm) * 32 * RED_STRIDE + red_base + g * 4];
                gs[g] = v;
            }
            float gf = gs[0] + xr[0];
            float gi = gs[1] + xr[1];
            float gc = gs[2] + xr[2];
            float go = gs[3] + xr[3];
            float cn = sigmf(gf) * creg + sigmf(gi) * tanhf(gc);
            creg = cn;
            float hn = sigmf(go) * tanhf(cn);
            __stcg(hw + hf_idx, tf32r(hn));
            out_hs[((size_t)rrow * SS + s) * HH + colg] = hn;
            if (s == SS - 1) {
                out[(size_t)rrow * HH + colg] = hn;
                out[(size_t)BB * HH + (size_t)rrow * HH + colg] = cn;
            }
        }

        // prefetch next step's xp before the barrier (hides L2 latency in the spin)
        if (s + 1 < SS) {
            #pragma unroll
            for (int g = 0; g < 4; g++)
                xr[g] = __ldg(g_xp + (size_t)((s + 1) * 64 + rrow) * NG + g * 1024 + colg);
        }

        // grid barrier (release h_new writes, acquire peers')
        __threadfence();
        __syncthreads();
        gen++;
        if (tid == 0) {
            unsigned t = atomicAdd(&g_cnt, 1u);
            if (t == gen * NCTA - 1u) {
                atomicExch(&g_gen, gen);
            } else {
                unsigned v;
                do {
                    asm volatile("ld.acquire.gpu.global.u32 %0, [%1];"
                                 : "=r"(v) : "l"(&g_gen) : "memory");
                } while (v < gen);
            }
            __threadfence();
        }
        __syncthreads();
    }
}

// ---------------- launch ----------------
extern "C" void kernel_launch(void* const* d_in, const int* in_sizes, int n_in,
                              void* d_out, int out_size)
{
    const float* x  = (const float*)d_in[0];
    const float* Uf = (const float*)d_in[1];
    const float* Ui = (const float*)d_in[2];
    const float* Uc = (const float*)d_in[3];
    const float* Uo = (const float*)d_in[4];
    const float* Wf = (const float*)d_in[5];
    const float* Wi = (const float*)d_in[6];
    const float* Wc = (const float*)d_in[7];
    const float* Wo = (const float*)d_in[8];
    const float* bf = (const float*)d_in[9];
    const float* bi = (const float*)d_in[10];
    const float* bc = (const float*)d_in[11];
    const float* bo = (const float*)d_in[12];
    float* out = (float*)d_out;

    static int smem_set = 0;
    if (!smem_set) {
        cudaFuncSetAttribute(lstm_persistent,
                             cudaFuncAttributeMaxDynamicSharedMemorySize, SM_TOTAL);
        smem_set = 1;
    }

    pack_kernel<<<dim3(32, 32, 8), dim3(32, 8)>>>(Uf, Ui, Uc, Uo, Wf, Wi, Wc, Wo);
    init_kernel<<<(64 * 1024 + 255) / 256, 256>>>();
    xproj_kernel<<<dim3(NG / 128, MMR / 128), 256>>>(x, bf, bi, bc, bo);

    float* hs = out + 2 * BB * HH;   // hidden_seq region
    lstm_persistent<<<NCTA, PTHR, SM_TOTAL>>>(out, hs);
}